// round 1
// baseline (speedup 1.0000x reference)
#include <cuda_runtime.h>

// ---------------------------------------------------------------------------
// S2Conv: out[b,g, off_l + u*d + m] = alpha * sum_e psi[e,g,l^2+u] * x[b,e,l^2+m]
// psi[e,g,i] = sum_n Y[n,i] * w[e,g,n] / sqrt(512),  alpha = 1/sqrt(64)
// Shapes: x (512,64,121), w (64,64,512), Y (512,121), out (512,64,1771)
// ---------------------------------------------------------------------------

#define LMAX  10
#define NI    121          // (LMAX+1)^2
#define FIN   64
#define FOUT  64
#define NGRID 512
#define BATCH 512
#define DTOT  1771         // sum_l (2l+1)^2
#define EG    4096         // FIN*FOUT

// combined scale: 1/(sqrt(512) * sqrt(64))
#define PSI_SCALE 0.005524271728019903f

// scratch: psi stored transposed as psi2[i][e*64+g]  (i-major, eg contiguous)
__device__ float g_psi[NI * EG];

// per-l tables
__constant__ int c_blk_start[12] = {0,8,80,280,672,1320,2288,3640,5440,7752,10640,14168};
__constant__ int c_off[11]       = {0,1,10,35,84,165,286,455,680,969,1330};

// ---------------------------------------------------------------------------
// Kernel 1: psi2[i][eg] = PSI_SCALE * sum_n Y[n,i] * w[eg,n]
// GEMM M=121 (pad 128), N=4096, K=512.  64 blocks x 256 threads.
// Block handles 64 eg columns, all 121 i rows. BK=32.
// ---------------------------------------------------------------------------
__global__ __launch_bounds__(256) void psi_kernel(const float* __restrict__ Y,
                                                  const float* __restrict__ W) {
    __shared__ float Ys[32 * 128];   // [n][i]  (i padded to 128)
    __shared__ float Ws[32 * 65];    // [n][eg_local], pad 65 for bank safety

    const int tid = threadIdx.x;
    const int tx  = tid & 15;        // eg quad: eg_local = tx*4 + j
    const int ty  = tid >> 4;        // i rows: i = ty + 16*r
    const int eg0 = blockIdx.x * 64;

    float acc[8][4];
    #pragma unroll
    for (int r = 0; r < 8; r++)
        #pragma unroll
        for (int j = 0; j < 4; j++) acc[r][j] = 0.f;

    for (int kk = 0; kk < NGRID; kk += 32) {
        // load Y tile: 32 x 128 (coalesced over i)
        #pragma unroll
        for (int it = 0; it < 16; it++) {
            int idx = it * 256 + tid;
            int n = idx >> 7, i = idx & 127;
            Ys[n * 128 + i] = (i < NI) ? Y[(kk + n) * NI + i] : 0.f;
        }
        // load W tile transposed: read coalesced over n, write [n][eg]
        #pragma unroll
        for (int it = 0; it < 8; it++) {
            int idx = it * 256 + tid;
            int egl = idx >> 5, n = idx & 31;
            Ws[n * 65 + egl] = W[(eg0 + egl) * NGRID + kk + n];
        }
        __syncthreads();

        #pragma unroll
        for (int n = 0; n < 32; n++) {
            float wv[4];
            #pragma unroll
            for (int j = 0; j < 4; j++) wv[j] = Ws[n * 65 + tx * 4 + j];
            #pragma unroll
            for (int r = 0; r < 8; r++) {
                float yv = Ys[n * 128 + ty + 16 * r];
                #pragma unroll
                for (int j = 0; j < 4; j++) acc[r][j] += yv * wv[j];
            }
        }
        __syncthreads();
    }

    #pragma unroll
    for (int r = 0; r < 8; r++) {
        int i = ty + 16 * r;
        if (i < NI) {
            float4 v = make_float4(acc[r][0] * PSI_SCALE, acc[r][1] * PSI_SCALE,
                                   acc[r][2] * PSI_SCALE, acc[r][3] * PSI_SCALE);
            *(float4*)&g_psi[i * EG + eg0 + tx * 4] = v;
        }
    }
}

// ---------------------------------------------------------------------------
// Kernel 2: per (l, u, row-tile) block.
// Block computes out tile: 64 rows (b,m flattened r = b*d+m) x 64 g, fixed u.
// acc[r][g] = sum_e Xs[e][r] * Ps[e][g]
// Thread map: tx = tid&15 -> rows rr = tx + 16*j (j=0..3, strided for
// coalesced stores along m); ty = tid>>4 -> g = ty*4 + j2 (float4 psi reads).
// ---------------------------------------------------------------------------
__global__ __launch_bounds__(256) void conv_kernel(const float* __restrict__ x,
                                                   float* __restrict__ out) {
    __shared__ float Ps[64 * 64];   // [e][g], contiguous copy of psi2 slice
    __shared__ float Xs[64 * 64];   // [e][rr]

    const int bid = blockIdx.x;

    // decode l from block id
    int l = 0;
    #pragma unroll
    for (int t = 1; t <= LMAX; t++)
        if (bid >= c_blk_start[t]) l = t;

    const int d   = 2 * l + 1;
    const int rel = bid - c_blk_start[l];
    const int nbr = 8 * d;               // row tiles per u
    const int u   = rel / nbr;
    const int r0  = (rel - u * nbr) * 64;
    const int l2  = l * l;

    const int tid = threadIdx.x;

    // load psi slice for (l2+u): 4096 contiguous floats
    {
        const float4* psrc = (const float4*)&g_psi[(l2 + u) * EG];
        float4* pdst = (float4*)Ps;
        #pragma unroll
        for (int it = 0; it < 4; it++)
            pdst[it * 256 + tid] = psrc[it * 256 + tid];
    }
    // load X tile: Xs[e][rr] = x[b, e, l2 + m] with r = r0+rr, b=r/d, m=r%d
    #pragma unroll
    for (int it = 0; it < 16; it++) {
        int idx = it * 256 + tid;
        int e = idx >> 6, rr = idx & 63;
        int r = r0 + rr;
        int b = r / d;
        int m = r - b * d;
        Xs[e * 64 + rr] = x[b * (FIN * NI) + e * NI + l2 + m];
    }
    __syncthreads();

    const int tx = tid & 15;
    const int ty = tid >> 4;

    float acc[4][4];
    #pragma unroll
    for (int j = 0; j < 4; j++)
        #pragma unroll
        for (int j2 = 0; j2 < 4; j2++) acc[j][j2] = 0.f;

    #pragma unroll 16
    for (int e = 0; e < 64; e++) {
        float4 p = *(const float4*)&Ps[e * 64 + ty * 4];
        float xv[4];
        #pragma unroll
        for (int j = 0; j < 4; j++) xv[j] = Xs[e * 64 + tx + 16 * j];
        #pragma unroll
        for (int j = 0; j < 4; j++) {
            acc[j][0] += xv[j] * p.x;
            acc[j][1] += xv[j] * p.y;
            acc[j][2] += xv[j] * p.z;
            acc[j][3] += xv[j] * p.w;
        }
    }

    // store: out[b*(FOUT*DTOT) + g*DTOT + off_l + u*d + m]
    const int offl = c_off[l];
    #pragma unroll
    for (int j = 0; j < 4; j++) {
        int r = r0 + tx + 16 * j;
        int b = r / d;
        int m = r - b * d;
        int base = b * (FOUT * DTOT) + offl + u * d + m;
        #pragma unroll
        for (int j2 = 0; j2 < 4; j2++)
            out[base + (ty * 4 + j2) * DTOT] = acc[j][j2];
    }
}

// ---------------------------------------------------------------------------
extern "C" void kernel_launch(void* const* d_in, const int* in_sizes, int n_in,
                              void* d_out, int out_size) {
    // identify inputs by element count (defensive against ordering)
    const float* x = nullptr;  // 512*64*121 = 3964928
    const float* w = nullptr;  // 64*64*512  = 2097152
    const float* Y = nullptr;  // 512*121    = 61952
    for (int i = 0; i < n_in; i++) {
        if (in_sizes[i] == BATCH * FIN * NI) x = (const float*)d_in[i];
        else if (in_sizes[i] == FIN * FOUT * NGRID) w = (const float*)d_in[i];
        else if (in_sizes[i] == NGRID * NI) Y = (const float*)d_in[i];
    }
    float* out = (float*)d_out;

    psi_kernel<<<64, 256>>>(Y, w);
    conv_kernel<<<14168, 256>>>(x, out);
}

// round 8
// speedup vs baseline: 1.4590x; 1.4590x over previous
#include <cuda_runtime.h>
#include <cuda_bf16.h>
#include <cstdint>

#define LMAX 10
#define NI   121
#define DTOT 1771
#define PSI_SCALE 0.005524271728019903f   // 1/(sqrt(512)*sqrt(64))

// scratch: packed bf16 (hi in low half, lo in high half) per fp32 value
__device__ uint32_t g_xt[512 * 64 * NI];   // [l-block][(b*d+m)][e]
__device__ uint32_t g_psi[NI * 4096];      // [i][g*64+e]

__constant__ int c_blk_start[12] = {0,4,40,140,336,660,1144,1820,2720,3876,5320,7084};
__constant__ int c_off[11]       = {0,1,10,35,84,165,286,455,680,969,1330};

// ---------------------------------------------------------------------------
__device__ __forceinline__ uint32_t su32(const void* p) {
    return (uint32_t)__cvta_generic_to_shared(p);
}
__device__ __forceinline__ uint32_t packsplit(float v) {
    __nv_bfloat16 h = __float2bfloat16(v);
    float rm = v - __bfloat162float(h);
    __nv_bfloat16 lo = __float2bfloat16(rm);
    return (uint32_t)__bfloat16_as_ushort(h)
         | ((uint32_t)__bfloat16_as_ushort(lo) << 16);
}
__device__ __forceinline__ void ldsm4(uint32_t* r, uint32_t addr) {
    asm volatile("ldmatrix.sync.aligned.m8n8.x4.shared.b16 {%0,%1,%2,%3}, [%4];"
                 : "=r"(r[0]), "=r"(r[1]), "=r"(r[2]), "=r"(r[3]) : "r"(addr));
}
__device__ __forceinline__ void mma16816(float* c, const uint32_t* a,
                                         uint32_t b0, uint32_t b1) {
    asm volatile(
        "mma.sync.aligned.m16n8k16.row.col.f32.bf16.bf16.f32 "
        "{%0,%1,%2,%3}, {%4,%5,%6,%7}, {%8,%9}, {%0,%1,%2,%3};"
        : "+f"(c[0]), "+f"(c[1]), "+f"(c[2]), "+f"(c[3])
        : "r"(a[0]), "r"(a[1]), "r"(a[2]), "r"(a[3]), "r"(b0), "r"(b1));
}

// ---------------------------------------------------------------------------
// Kernel 1: g_psi[i][g*64+e] = pack( SCALE * sum_n Y[n,i] * w[e,g,n] )
// ---------------------------------------------------------------------------
__global__ __launch_bounds__(256) void psi_kernel(const float* __restrict__ Y,
                                                  const float* __restrict__ W) {
    __shared__ float Ys[32 * 128];
    __shared__ float Ws[32 * 17];

    const int tid = threadIdx.x;
    const int tx  = tid & 3;
    const int ty  = tid >> 2;
    const int c0  = blockIdx.x * 16;
    const int g   = c0 >> 6;
    const int eb  = c0 & 63;

    float acc0[4] = {0.f, 0.f, 0.f, 0.f};
    float acc1[4] = {0.f, 0.f, 0.f, 0.f};

    for (int kk = 0; kk < 512; kk += 32) {
        #pragma unroll
        for (int it = 0; it < 16; it++) {
            int idx = it * 256 + tid;
            int n = idx >> 7, i = idx & 127;
            Ys[n * 128 + i] = (i < NI) ? Y[(kk + n) * NI + i] : 0.f;
        }
        #pragma unroll
        for (int it = 0; it < 2; it++) {
            int idx = it * 256 + tid;
            int cl = idx >> 5, n = idx & 31;
            Ws[n * 17 + cl] = W[(eb + cl) * 32768 + g * 512 + kk + n];
        }
        __syncthreads();

        #pragma unroll
        for (int n = 0; n < 32; n++) {
            float wv[4];
            #pragma unroll
            for (int j = 0; j < 4; j++) wv[j] = Ws[n * 17 + tx * 4 + j];
            float y0 = Ys[n * 128 + ty];
            float y1 = Ys[n * 128 + ty + 64];
            #pragma unroll
            for (int j = 0; j < 4; j++) {
                acc0[j] += y0 * wv[j];
                acc1[j] += y1 * wv[j];
            }
        }
        __syncthreads();
    }

    uint4 v0;
    v0.x = packsplit(acc0[0] * PSI_SCALE);
    v0.y = packsplit(acc0[1] * PSI_SCALE);
    v0.z = packsplit(acc0[2] * PSI_SCALE);
    v0.w = packsplit(acc0[3] * PSI_SCALE);
    *(uint4*)&g_psi[ty * 4096 + c0 + tx * 4] = v0;
    if (ty + 64 < NI) {
        uint4 v1;
        v1.x = packsplit(acc1[0] * PSI_SCALE);
        v1.y = packsplit(acc1[1] * PSI_SCALE);
        v1.z = packsplit(acc1[2] * PSI_SCALE);
        v1.w = packsplit(acc1[3] * PSI_SCALE);
        *(uint4*)&g_psi[(ty + 64) * 4096 + c0 + tx * 4] = v1;
    }
}

// ---------------------------------------------------------------------------
// Kernel 2: transpose + split x[b][e][i] -> g_xt[32768*l^2 + (b*d+m)*64 + e]
// ---------------------------------------------------------------------------
__global__ __launch_bounds__(256) void transpose_kernel(const float* __restrict__ x) {
    __shared__ float s[64 * NI];
    const int b = blockIdx.x, tid = threadIdx.x;
    const float* xb = x + b * (64 * NI);

    for (int k = tid; k < 64 * NI; k += 256) s[k] = xb[k];
    __syncthreads();

    for (int k = tid; k < 64 * NI; k += 256) {
        int i = k >> 6, e = k & 63;
        float v = s[e * NI + i];
        int l = (int)sqrtf((float)i + 0.5f);
        int d = 2 * l + 1, m = i - l * l;
        g_xt[32768 * l * l + (b * d + m) * 64 + e] = packsplit(v);
    }
}

// ---------------------------------------------------------------------------
// Kernel 3: 3-term bf16 split GEMM: D = Ah*Bh + Ah*Bl + Al*Bh.
// Tile (l,u,mtile): M=128 rows of (b,m), N=64 (g), K=64 (e).
// 256 threads = 8 warps, warp tile 32x32.
// SMEM rows: 64 bf16 = 128B data, padded to 144B (9x16B chunks, conflict-free).
// ---------------------------------------------------------------------------
#define AST     144
#define OFF_AL  18432      // 128*144
#define OFF_BH  36864
#define OFF_BL  46080      // +64*144
#define DSMEM   55296

__global__ __launch_bounds__(256) void conv_kernel(float* __restrict__ out) {
    extern __shared__ __align__(16) char sb[];

    const int tid  = threadIdx.x;
    const int wid  = tid >> 5;
    const int lane = tid & 31;
    const int bid  = blockIdx.x;

    int l = 0;
    #pragma unroll
    for (int t = 1; t <= LMAX; t++)
        if (bid >= c_blk_start[t]) l = t;
    const int d   = 2 * l + 1;
    const int l2  = l * l;
    const int rel = bid - c_blk_start[l];
    const int u   = rel / (4 * d);
    const int r0  = (rel - u * 4 * d) * 128;

    // ---- load A: 128 rows x 64 packed e -> unpack into Ah / Al
    {
        const uint4* asrc = (const uint4*)(g_xt + l2 * 32768 + r0 * 64);
        #pragma unroll
        for (int it = 0; it < 8; it++) {
            int idx = it * 256 + tid;
            int r = idx >> 4, j = idx & 15;
            uint4 v = asrc[idx];
            uint2 hi, lo;
            hi.x = __byte_perm(v.x, v.y, 0x5410);
            hi.y = __byte_perm(v.z, v.w, 0x5410);
            lo.x = __byte_perm(v.x, v.y, 0x7632);
            lo.y = __byte_perm(v.z, v.w, 0x7632);
            *(uint2*)(sb + r * AST + j * 8)          = hi;
            *(uint2*)(sb + OFF_AL + r * AST + j * 8) = lo;
        }
        const uint4* bsrc = (const uint4*)(g_psi + (l2 + u) * 4096);
        #pragma unroll
        for (int it = 0; it < 4; it++) {
            int idx = it * 256 + tid;
            int n = idx >> 4, j = idx & 15;
            uint4 v = bsrc[idx];
            uint2 hi, lo;
            hi.x = __byte_perm(v.x, v.y, 0x5410);
            hi.y = __byte_perm(v.z, v.w, 0x5410);
            lo.x = __byte_perm(v.x, v.y, 0x7632);
            lo.y = __byte_perm(v.z, v.w, 0x7632);
            *(uint2*)(sb + OFF_BH + n * AST + j * 8) = hi;
            *(uint2*)(sb + OFF_BL + n * AST + j * 8) = lo;
        }
    }
    __syncthreads();

    // ---- mainloop
    const int wm = wid & 3;           // 4 m-blocks of 32
    const int wn = wid >> 2;          // 2 n-blocks of 32
    const uint32_t rowA = (wm * 32 + (lane & 15)) * AST + (lane >> 4) * 16;
    const uint32_t rowB = (wn * 32 + (lane & 15)) * AST + (lane >> 4) * 16;
    const uint32_t aHi = su32(sb) + rowA;
    const uint32_t aLo = su32(sb) + OFF_AL + rowA;
    const uint32_t bHi = su32(sb) + OFF_BH + rowB;
    const uint32_t bLo = su32(sb) + OFF_BL + rowB;

    float acc[2][4][4];
    #pragma unroll
    for (int mt = 0; mt < 2; mt++)
        #pragma unroll
        for (int nt = 0; nt < 4; nt++)
            #pragma unroll
            for (int q = 0; q < 4; q++) acc[mt][nt][q] = 0.f;

    #pragma unroll
    for (int ks = 0; ks < 4; ks++) {
        const uint32_t kb = ks * 32;
        uint32_t ah[2][4], al[2][4], bh[2][4], bl[2][4];
        ldsm4(ah[0], aHi + kb);
        ldsm4(ah[1], aHi + 16 * AST + kb);
        ldsm4(al[0], aLo + kb);
        ldsm4(al[1], aLo + 16 * AST + kb);
        ldsm4(bh[0], bHi + kb);
        ldsm4(bh[1], bHi + 16 * AST + kb);
        ldsm4(bl[0], bLo + kb);
        ldsm4(bl[1], bLo + 16 * AST + kb);
        #pragma unroll
        for (int mt = 0; mt < 2; mt++) {
            #pragma unroll
            for (int h = 0; h < 2; h++) {
                // hh
                mma16816(acc[mt][2 * h + 0], ah[mt], bh[h][0], bh[h][2]);
                mma16816(acc[mt][2 * h + 1], ah[mt], bh[h][1], bh[h][3]);
                // hl
                mma16816(acc[mt][2 * h + 0], ah[mt], bl[h][0], bl[h][2]);
                mma16816(acc[mt][2 * h + 1], ah[mt], bl[h][1], bl[h][3]);
                // lh
                mma16816(acc[mt][2 * h + 0], al[mt], bh[h][0], bh[h][2]);
                mma16816(acc[mt][2 * h + 1], al[mt], bh[h][1], bh[h][3]);
            }
        }
    }

    // ---- epilogue: stage fp32 tile in smem, stride 65
    __syncthreads();
    float* sC = (float*)sb;
    const int gID = lane >> 2;
    const int tig = lane & 3;
    #pragma unroll
    for (int mt = 0; mt < 2; mt++) {
        #pragma unroll
        for (int nt = 0; nt < 4; nt++) {
            int row = wm * 32 + mt * 16 + gID;
            int col = wn * 32 + nt * 8 + tig * 2;
            sC[row * 65 + col]           = acc[mt][nt][0];
            sC[row * 65 + col + 1]       = acc[mt][nt][1];
            sC[(row + 8) * 65 + col]     = acc[mt][nt][2];
            sC[(row + 8) * 65 + col + 1] = acc[mt][nt][3];
        }
    }
    __syncthreads();

    const int offl = c_off[l];
    #pragma unroll
    for (int it = 0; it < 32; it++) {
        int linear = it * 256 + tid;
        int g = linear >> 7;
        int r = linear & 127;
        int R = r0 + r;
        int b = R / d;
        int m = R - b * d;
        out[(size_t)b * (64 * DTOT) + (size_t)g * DTOT + offl + u * d + m]
            = sC[r * 65 + g];
    }
}

// ---------------------------------------------------------------------------
extern "C" void kernel_launch(void* const* d_in, const int* in_sizes, int n_in,
                              void* d_out, int out_size) {
    const float *x = nullptr, *w = nullptr, *Y = nullptr;
    for (int i = 0; i < n_in; i++) {
        if (in_sizes[i] == 512 * 64 * NI)       x = (const float*)d_in[i];
        else if (in_sizes[i] == 64 * 64 * 512)  w = (const float*)d_in[i];
        else if (in_sizes[i] == 512 * NI)       Y = (const float*)d_in[i];
    }
    float* out = (float*)d_out;

    cudaFuncSetAttribute(conv_kernel, cudaFuncAttributeMaxDynamicSharedMemorySize, DSMEM);

    psi_kernel<<<256, 256>>>(Y, w);
    transpose_kernel<<<512, 256>>>(x);
    conv_kernel<<<7084, 256, DSMEM>>>(out);
}

// round 10
// speedup vs baseline: 1.6251x; 1.1138x over previous
#include <cuda_runtime.h>
#include <cuda_bf16.h>
#include <cstdint>

#define LMAX 10
#define NI   121
#define DTOT 1771
#define PSI_SCALE 0.005524271728019903f   // 1/(sqrt(512)*sqrt(64))

// scratch: packed bf16 (hi in low half, lo in high half) per fp32 value
__device__ uint32_t g_xt[512 * 64 * NI];   // [l-block][(b*d+m)][e]
__device__ uint32_t g_psi[NI * 4096];      // [i][g*64+e]

__constant__ int c_blk_start[12] = {0,4,40,140,336,660,1144,1820,2720,3876,5320,7084};
__constant__ int c_off[11]       = {0,1,10,35,84,165,286,455,680,969,1330};

// ---------------------------------------------------------------------------
__device__ __forceinline__ uint32_t su32(const void* p) {
    return (uint32_t)__cvta_generic_to_shared(p);
}
__device__ __forceinline__ uint32_t packsplit(float v) {
    __nv_bfloat16 h = __float2bfloat16(v);
    float rm = v - __bfloat162float(h);
    __nv_bfloat16 lo = __float2bfloat16(rm);
    return (uint32_t)__bfloat16_as_ushort(h)
         | ((uint32_t)__bfloat16_as_ushort(lo) << 16);
}
__device__ __forceinline__ void ldsm4(uint32_t* r, uint32_t addr) {
    asm volatile("ldmatrix.sync.aligned.m8n8.x4.shared.b16 {%0,%1,%2,%3}, [%4];"
                 : "=r"(r[0]), "=r"(r[1]), "=r"(r[2]), "=r"(r[3]) : "r"(addr));
}
__device__ __forceinline__ void mma16816(float* c, const uint32_t* a,
                                         uint32_t b0, uint32_t b1) {
    asm volatile(
        "mma.sync.aligned.m16n8k16.row.col.f32.bf16.bf16.f32 "
        "{%0,%1,%2,%3}, {%4,%5,%6,%7}, {%8,%9}, {%0,%1,%2,%3};"
        : "+f"(c[0]), "+f"(c[1]), "+f"(c[2]), "+f"(c[3])
        : "r"(a[0]), "r"(a[1]), "r"(a[2]), "r"(a[3]), "r"(b0), "r"(b1));
}

// shared tile geometry (row = 64 bf16 = 128B, padded to 144B = 9x16B chunks)
#define AST     144
#define OFF_AL  18432      // 128*144
#define OFF_BH  36864
#define OFF_BL  46080      // +64*144
#define DSMEM   55296

// ---------------------------------------------------------------------------
// Kernel 1: psi via tensor cores.
// Per block: g = blockIdx.x. C[i][e] = SCALE * sum_n Y[n][i] * W[(e*64+g)*512+n]
// M=128 (i, 121 live), N=64 (e), K=512 in 8 chunks of 64.
// 3-term bf16 split per chunk. Output packed into g_psi[i][g*64+e].
// ---------------------------------------------------------------------------
__global__ __launch_bounds__(256) void psi_mma_kernel(const float* __restrict__ Y,
                                                      const float* __restrict__ W) {
    extern __shared__ __align__(16) char sb[];

    const int tid  = threadIdx.x;
    const int wid  = tid >> 5;
    const int lane = tid & 31;
    const int g    = blockIdx.x;

    const int wm = wid & 3;
    const int wn = wid >> 2;
    const uint32_t rowA = (wm * 32 + (lane & 15)) * AST + (lane >> 4) * 16;
    const uint32_t rowB = (wn * 32 + (lane & 15)) * AST + (lane >> 4) * 16;
    const uint32_t aHi = su32(sb) + rowA;
    const uint32_t aLo = su32(sb) + OFF_AL + rowA;
    const uint32_t bHi = su32(sb) + OFF_BH + rowB;
    const uint32_t bLo = su32(sb) + OFF_BL + rowB;

    float acc[2][4][4];
    #pragma unroll
    for (int mt = 0; mt < 2; mt++)
        #pragma unroll
        for (int nt = 0; nt < 4; nt++)
            #pragma unroll
            for (int q = 0; q < 4; q++) acc[mt][nt][q] = 0.f;

    for (int kk = 0; kk < 512; kk += 64) {
        // A tile: [i][k], i<121 live; load Y[(kk+k)*121 + i], 2 k per thread-pass
        #pragma unroll
        for (int it = 0; it < 16; it++) {
            int idx = it * 256 + tid;
            int kp = idx >> 7;          // k pair index 0..31
            int i  = idx & 127;
            float v0 = 0.f, v1 = 0.f;
            if (i < NI) {
                v0 = Y[(kk + 2 * kp) * NI + i];
                v1 = Y[(kk + 2 * kp + 1) * NI + i];
            }
            __nv_bfloat16 h0 = __float2bfloat16(v0);
            __nv_bfloat16 h1 = __float2bfloat16(v1);
            __nv_bfloat16 l0 = __float2bfloat16(v0 - __bfloat162float(h0));
            __nv_bfloat16 l1 = __float2bfloat16(v1 - __bfloat162float(h1));
            uint32_t hw = (uint32_t)__bfloat16_as_ushort(h0)
                        | ((uint32_t)__bfloat16_as_ushort(h1) << 16);
            uint32_t lw = (uint32_t)__bfloat16_as_ushort(l0)
                        | ((uint32_t)__bfloat16_as_ushort(l1) << 16);
            *(uint32_t*)(sb + i * AST + kp * 4)          = hw;
            *(uint32_t*)(sb + OFF_AL + i * AST + kp * 4) = lw;
        }
        // B tile: [e][k], W[(e*64+g)*512 + kk + k]
        #pragma unroll
        for (int it = 0; it < 4; it++) {
            int idx = it * 256 + tid;
            int e = idx >> 4, j = idx & 15;
            float4 v = *(const float4*)&W[(size_t)(e * 64 + g) * 512 + kk + j * 4];
            __nv_bfloat16 h0 = __float2bfloat16(v.x), h1 = __float2bfloat16(v.y);
            __nv_bfloat16 h2 = __float2bfloat16(v.z), h3 = __float2bfloat16(v.w);
            __nv_bfloat16 l0 = __float2bfloat16(v.x - __bfloat162float(h0));
            __nv_bfloat16 l1 = __float2bfloat16(v.y - __bfloat162float(h1));
            __nv_bfloat16 l2 = __float2bfloat16(v.z - __bfloat162float(h2));
            __nv_bfloat16 l3 = __float2bfloat16(v.w - __bfloat162float(h3));
            uint2 hi, lo;
            hi.x = (uint32_t)__bfloat16_as_ushort(h0) | ((uint32_t)__bfloat16_as_ushort(h1) << 16);
            hi.y = (uint32_t)__bfloat16_as_ushort(h2) | ((uint32_t)__bfloat16_as_ushort(h3) << 16);
            lo.x = (uint32_t)__bfloat16_as_ushort(l0) | ((uint32_t)__bfloat16_as_ushort(l1) << 16);
            lo.y = (uint32_t)__bfloat16_as_ushort(l2) | ((uint32_t)__bfloat16_as_ushort(l3) << 16);
            *(uint2*)(sb + OFF_BH + e * AST + j * 8) = hi;
            *(uint2*)(sb + OFF_BL + e * AST + j * 8) = lo;
        }
        __syncthreads();

        #pragma unroll
        for (int ks = 0; ks < 4; ks++) {
            const uint32_t kb = ks * 32;
            uint32_t ah[2][4], al[2][4], bh[2][4], bl[2][4];
            ldsm4(ah[0], aHi + kb);
            ldsm4(ah[1], aHi + 16 * AST + kb);
            ldsm4(al[0], aLo + kb);
            ldsm4(al[1], aLo + 16 * AST + kb);
            ldsm4(bh[0], bHi + kb);
            ldsm4(bh[1], bHi + 16 * AST + kb);
            ldsm4(bl[0], bLo + kb);
            ldsm4(bl[1], bLo + 16 * AST + kb);
            #pragma unroll
            for (int mt = 0; mt < 2; mt++) {
                #pragma unroll
                for (int h = 0; h < 2; h++) {
                    mma16816(acc[mt][2 * h + 0], ah[mt], bh[h][0], bh[h][2]);
                    mma16816(acc[mt][2 * h + 1], ah[mt], bh[h][1], bh[h][3]);
                    mma16816(acc[mt][2 * h + 0], ah[mt], bl[h][0], bl[h][2]);
                    mma16816(acc[mt][2 * h + 1], ah[mt], bl[h][1], bl[h][3]);
                    mma16816(acc[mt][2 * h + 0], al[mt], bh[h][0], bh[h][2]);
                    mma16816(acc[mt][2 * h + 1], al[mt], bh[h][1], bh[h][3]);
                }
            }
        }
        __syncthreads();
    }

    // epilogue: pack+store direct to g_psi[i*4096 + g*64 + e]
    const int gID = lane >> 2;
    const int tig = lane & 3;
    #pragma unroll
    for (int mt = 0; mt < 2; mt++) {
        #pragma unroll
        for (int nt = 0; nt < 4; nt++) {
            int row = wm * 32 + mt * 16 + gID;
            int col = wn * 32 + nt * 8 + tig * 2;
            if (row < NI) {
                g_psi[row * 4096 + g * 64 + col]     = packsplit(acc[mt][nt][0] * PSI_SCALE);
                g_psi[row * 4096 + g * 64 + col + 1] = packsplit(acc[mt][nt][1] * PSI_SCALE);
            }
            if (row + 8 < NI) {
                g_psi[(row + 8) * 4096 + g * 64 + col]     = packsplit(acc[mt][nt][2] * PSI_SCALE);
                g_psi[(row + 8) * 4096 + g * 64 + col + 1] = packsplit(acc[mt][nt][3] * PSI_SCALE);
            }
        }
    }
}

// ---------------------------------------------------------------------------
// Kernel 2: transpose + split x[b][e][i] -> g_xt[32768*l^2 + (b*d+m)*64 + e]
// ---------------------------------------------------------------------------
__global__ __launch_bounds__(256) void transpose_kernel(const float* __restrict__ x) {
    __shared__ float s[64 * NI];
    const int b = blockIdx.x, tid = threadIdx.x;
    const float* xb = x + b * (64 * NI);

    for (int k = tid; k < 64 * NI; k += 256) s[k] = xb[k];
    __syncthreads();

    for (int k = tid; k < 64 * NI; k += 256) {
        int i = k >> 6, e = k & 63;
        float v = s[e * NI + i];
        int l = (int)sqrtf((float)i + 0.5f);
        int d = 2 * l + 1, m = i - l * l;
        g_xt[32768 * l * l + (b * d + m) * 64 + e] = packsplit(v);
    }
}

// ---------------------------------------------------------------------------
// Kernel 3: 3-term bf16 split GEMM: D = Ah*Bh + Ah*Bl + Al*Bh.
// Tile (l, mtile, u): consecutive bids share the A tile (u fastest) -> L2 reuse.
// M=128 rows of (b,m), N=64 (g), K=64 (e). 8 warps, warp tile 32x32.
// ---------------------------------------------------------------------------
__global__ __launch_bounds__(256) void conv_kernel(float* __restrict__ out) {
    extern __shared__ __align__(16) char sb[];

    const int tid  = threadIdx.x;
    const int wid  = tid >> 5;
    const int lane = tid & 31;
    const int bid  = blockIdx.x;

    int l = 0;
    #pragma unroll
    for (int t = 1; t <= LMAX; t++)
        if (bid >= c_blk_start[t]) l = t;
    const int d     = 2 * l + 1;
    const int l2    = l * l;
    const int rel   = bid - c_blk_start[l];
    const int mtile = rel / d;            // A tile id (u fastest-varying)
    const int u     = rel - mtile * d;
    const int r0    = mtile * 128;

    // ---- load A: 128 rows x 64 packed e -> unpack into Ah / Al
    {
        const uint4* asrc = (const uint4*)(g_xt + l2 * 32768 + r0 * 64);
        #pragma unroll
        for (int it = 0; it < 8; it++) {
            int idx = it * 256 + tid;
            int r = idx >> 4, j = idx & 15;
            uint4 v = asrc[idx];
            uint2 hi, lo;
            hi.x = __byte_perm(v.x, v.y, 0x5410);
            hi.y = __byte_perm(v.z, v.w, 0x5410);
            lo.x = __byte_perm(v.x, v.y, 0x7632);
            lo.y = __byte_perm(v.z, v.w, 0x7632);
            *(uint2*)(sb + r * AST + j * 8)          = hi;
            *(uint2*)(sb + OFF_AL + r * AST + j * 8) = lo;
        }
        const uint4* bsrc = (const uint4*)(g_psi + (l2 + u) * 4096);
        #pragma unroll
        for (int it = 0; it < 4; it++) {
            int idx = it * 256 + tid;
            int n = idx >> 4, j = idx & 15;
            uint4 v = bsrc[idx];
            uint2 hi, lo;
            hi.x = __byte_perm(v.x, v.y, 0x5410);
            hi.y = __byte_perm(v.z, v.w, 0x5410);
            lo.x = __byte_perm(v.x, v.y, 0x7632);
            lo.y = __byte_perm(v.z, v.w, 0x7632);
            *(uint2*)(sb + OFF_BH + n * AST + j * 8) = hi;
            *(uint2*)(sb + OFF_BL + n * AST + j * 8) = lo;
        }
    }
    __syncthreads();

    const int wm = wid & 3;
    const int wn = wid >> 2;
    const uint32_t rowA = (wm * 32 + (lane & 15)) * AST + (lane >> 4) * 16;
    const uint32_t rowB = (wn * 32 + (lane & 15)) * AST + (lane >> 4) * 16;
    const uint32_t aHi = su32(sb) + rowA;
    const uint32_t aLo = su32(sb) + OFF_AL + rowA;
    const uint32_t bHi = su32(sb) + OFF_BH + rowB;
    const uint32_t bLo = su32(sb) + OFF_BL + rowB;

    float acc[2][4][4];
    #pragma unroll
    for (int mt = 0; mt < 2; mt++)
        #pragma unroll
        for (int nt = 0; nt < 4; nt++)
            #pragma unroll
            for (int q = 0; q < 4; q++) acc[mt][nt][q] = 0.f;

    #pragma unroll
    for (int ks = 0; ks < 4; ks++) {
        const uint32_t kb = ks * 32;
        uint32_t ah[2][4], al[2][4], bh[2][4], bl[2][4];
        ldsm4(ah[0], aHi + kb);
        ldsm4(ah[1], aHi + 16 * AST + kb);
        ldsm4(al[0], aLo + kb);
        ldsm4(al[1], aLo + 16 * AST + kb);
        ldsm4(bh[0], bHi + kb);
        ldsm4(bh[1], bHi + 16 * AST + kb);
        ldsm4(bl[0], bLo + kb);
        ldsm4(bl[1], bLo + 16 * AST + kb);
        #pragma unroll
        for (int mt = 0; mt < 2; mt++) {
            #pragma unroll
            for (int h = 0; h < 2; h++) {
                mma16816(acc[mt][2 * h + 0], ah[mt], bh[h][0], bh[h][2]);
                mma16816(acc[mt][2 * h + 1], ah[mt], bh[h][1], bh[h][3]);
                mma16816(acc[mt][2 * h + 0], ah[mt], bl[h][0], bl[h][2]);
                mma16816(acc[mt][2 * h + 1], ah[mt], bl[h][1], bl[h][3]);
                mma16816(acc[mt][2 * h + 0], al[mt], bh[h][0], bh[h][2]);
                mma16816(acc[mt][2 * h + 1], al[mt], bh[h][1], bh[h][3]);
            }
        }
    }

    // ---- epilogue: stage fp32 tile in smem, stride 65
    __syncthreads();
    float* sC = (float*)sb;
    const int gID = lane >> 2;
    const int tig = lane & 3;
    #pragma unroll
    for (int mt = 0; mt < 2; mt++) {
        #pragma unroll
        for (int nt = 0; nt < 4; nt++) {
            int row = wm * 32 + mt * 16 + gID;
            int col = wn * 32 + nt * 8 + tig * 2;
            sC[row * 65 + col]           = acc[mt][nt][0];
            sC[row * 65 + col + 1]       = acc[mt][nt][1];
            sC[(row + 8) * 65 + col]     = acc[mt][nt][2];
            sC[(row + 8) * 65 + col + 1] = acc[mt][nt][3];
        }
    }
    __syncthreads();

    const int offl = c_off[l];
    #pragma unroll
    for (int it = 0; it < 32; it++) {
        int linear = it * 256 + tid;
        int g = linear >> 7;
        int r = linear & 127;
        int R = r0 + r;
        int b = R / d;
        int m = R - b * d;
        out[(size_t)b * (64 * DTOT) + (size_t)g * DTOT + offl + u * d + m]
            = sC[r * 65 + g];
    }
}

// ---------------------------------------------------------------------------
extern "C" void kernel_launch(void* const* d_in, const int* in_sizes, int n_in,
                              void* d_out, int out_size) {
    const float *x = nullptr, *w = nullptr, *Y = nullptr;
    for (int i = 0; i < n_in; i++) {
        if (in_sizes[i] == 512 * 64 * NI)       x = (const float*)d_in[i];
        else if (in_sizes[i] == 64 * 64 * 512)  w = (const float*)d_in[i];
        else if (in_sizes[i] == 512 * NI)       Y = (const float*)d_in[i];
    }
    float* out = (float*)d_out;

    cudaFuncSetAttribute(psi_mma_kernel, cudaFuncAttributeMaxDynamicSharedMemorySize, DSMEM);
    cudaFuncSetAttribute(conv_kernel,    cudaFuncAttributeMaxDynamicSharedMemorySize, DSMEM);

    psi_mma_kernel<<<64, 256, DSMEM>>>(Y, w);
    transpose_kernel<<<512, 256>>>(x);
    conv_kernel<<<7084, 256, DSMEM>>>(out);
}

// round 11
// speedup vs baseline: 1.7721x; 1.0904x over previous
#include <cuda_runtime.h>
#include <cuda_bf16.h>
#include <cstdint>

#define LMAX 10
#define NI   121
#define DTOT 1771
#define PSI_SCALE 0.005524271728019903f   // 1/(sqrt(512)*sqrt(64))

// scratch: packed bf16 (hi low half, lo high half) per fp32 value
__device__ uint32_t g_xt[512 * 64 * NI];   // [l-block][(b*d+m)][e]
__device__ uint32_t g_psi[NI * 4096];      // [i][g*64+e]
__device__ float    g_psif[4 * NI * 4096]; // k-split partials [ks][i][g*64+e]

__constant__ int c_blk_start[12] = {0,4,40,140,336,660,1144,1820,2720,3876,5320,7084};
__constant__ int c_off[11]       = {0,1,10,35,84,165,286,455,680,969,1330};

// ---------------------------------------------------------------------------
__device__ __forceinline__ uint32_t su32(const void* p) {
    return (uint32_t)__cvta_generic_to_shared(p);
}
__device__ __forceinline__ uint32_t packsplit(float v) {
    __nv_bfloat16 h = __float2bfloat16(v);
    float rm = v - __bfloat162float(h);
    __nv_bfloat16 lo = __float2bfloat16(rm);
    return (uint32_t)__bfloat16_as_ushort(h)
         | ((uint32_t)__bfloat16_as_ushort(lo) << 16);
}
__device__ __forceinline__ void ldsm4(uint32_t* r, uint32_t addr) {
    asm volatile("ldmatrix.sync.aligned.m8n8.x4.shared.b16 {%0,%1,%2,%3}, [%4];"
                 : "=r"(r[0]), "=r"(r[1]), "=r"(r[2]), "=r"(r[3]) : "r"(addr));
}
__device__ __forceinline__ void mma16816(float* c, const uint32_t* a,
                                         uint32_t b0, uint32_t b1) {
    asm volatile(
        "mma.sync.aligned.m16n8k16.row.col.f32.bf16.bf16.f32 "
        "{%0,%1,%2,%3}, {%4,%5,%6,%7}, {%8,%9}, {%0,%1,%2,%3};"
        : "+f"(c[0]), "+f"(c[1]), "+f"(c[2]), "+f"(c[3])
        : "r"(a[0]), "r"(a[1]), "r"(a[2]), "r"(a[3]), "r"(b0), "r"(b1));
}

// shared tile geometry (row = 64 bf16 = 128B, padded to 144B = 9x16B chunks)
#define AST     144
#define OFF_AL  18432      // 128*144
#define OFF_BH  36864
#define OFF_BL  46080      // +64*144
#define DSMEM   55296

// term-major MMA block: 8 independent accs per term -> no RAW stalls
#define MMA_TERM(A, B)                                                   \
    do {                                                                 \
        _Pragma("unroll")                                                \
        for (int mt = 0; mt < 2; mt++) {                                 \
            _Pragma("unroll")                                            \
            for (int h = 0; h < 2; h++) {                                \
                mma16816(acc[mt][2 * h + 0], A[mt], B[h][0], B[h][2]);   \
                mma16816(acc[mt][2 * h + 1], A[mt], B[h][1], B[h][3]);   \
            }                                                            \
        }                                                                \
    } while (0)

// ---------------------------------------------------------------------------
// Fused kernel: blocks [0,256) = psi k-split partial GEMM, [256,768) = x transpose.
// psi block: g = bid&63, ks = bid>>6. C_ks[i][e] = sum_{n in ks chunk} Y[n,i]*W[(e,g),n]
//   M=128 (121 live i), N=64 (e), K=128 (2 sub-chunks of 64), 3-term bf16 split.
// ---------------------------------------------------------------------------
__global__ __launch_bounds__(256) void fused_pre_kernel(const float* __restrict__ Y,
                                                        const float* __restrict__ W,
                                                        const float* __restrict__ x) {
    extern __shared__ __align__(16) char sb[];
    const int tid = threadIdx.x;

    if (blockIdx.x >= 256) {
        // ---------------- transpose role ----------------
        float* s = (float*)sb;
        const int b = blockIdx.x - 256;
        const float* xb = x + b * (64 * NI);
        for (int k = tid; k < 64 * NI; k += 256) s[k] = xb[k];
        __syncthreads();
        for (int k = tid; k < 64 * NI; k += 256) {
            int i = k >> 6, e = k & 63;
            float v = s[e * NI + i];
            int l = (int)sqrtf((float)i + 0.5f);
            int d = 2 * l + 1, m = i - l * l;
            g_xt[32768 * l * l + (b * d + m) * 64 + e] = packsplit(v);
        }
        return;
    }

    // ---------------- psi partial role ----------------
    const int wid  = tid >> 5;
    const int lane = tid & 31;
    const int g    = blockIdx.x & 63;
    const int ks   = blockIdx.x >> 6;
    const int k0   = ks * 128;

    const int wm = wid & 3;
    const int wn = wid >> 2;
    const uint32_t rowA = (wm * 32 + (lane & 15)) * AST + (lane >> 4) * 16;
    const uint32_t rowB = (wn * 32 + (lane & 15)) * AST + (lane >> 4) * 16;
    const uint32_t aHi = su32(sb) + rowA;
    const uint32_t aLo = su32(sb) + OFF_AL + rowA;
    const uint32_t bHi = su32(sb) + OFF_BH + rowB;
    const uint32_t bLo = su32(sb) + OFF_BL + rowB;

    float acc[2][4][4];
    #pragma unroll
    for (int mt = 0; mt < 2; mt++)
        #pragma unroll
        for (int nt = 0; nt < 4; nt++)
            #pragma unroll
            for (int q = 0; q < 4; q++) acc[mt][nt][q] = 0.f;

    for (int kc = 0; kc < 2; kc++) {
        const int kk = k0 + kc * 64;
        // A tile: [i][k] from Y[(kk+k)*121 + i]
        #pragma unroll
        for (int it = 0; it < 16; it++) {
            int idx = it * 256 + tid;
            int kp = idx >> 7;
            int i  = idx & 127;
            float v0 = 0.f, v1 = 0.f;
            if (i < NI) {
                v0 = Y[(kk + 2 * kp) * NI + i];
                v1 = Y[(kk + 2 * kp + 1) * NI + i];
            }
            __nv_bfloat16 h0 = __float2bfloat16(v0);
            __nv_bfloat16 h1 = __float2bfloat16(v1);
            __nv_bfloat16 l0 = __float2bfloat16(v0 - __bfloat162float(h0));
            __nv_bfloat16 l1 = __float2bfloat16(v1 - __bfloat162float(h1));
            *(uint32_t*)(sb + i * AST + kp * 4) =
                (uint32_t)__bfloat16_as_ushort(h0) | ((uint32_t)__bfloat16_as_ushort(h1) << 16);
            *(uint32_t*)(sb + OFF_AL + i * AST + kp * 4) =
                (uint32_t)__bfloat16_as_ushort(l0) | ((uint32_t)__bfloat16_as_ushort(l1) << 16);
        }
        // B tile: [e][k] from W[(e*64+g)*512 + kk + k]
        #pragma unroll
        for (int it = 0; it < 4; it++) {
            int idx = it * 256 + tid;
            int e = idx >> 4, j = idx & 15;
            float4 v = *(const float4*)&W[(size_t)(e * 64 + g) * 512 + kk + j * 4];
            __nv_bfloat16 h0 = __float2bfloat16(v.x), h1 = __float2bfloat16(v.y);
            __nv_bfloat16 h2 = __float2bfloat16(v.z), h3 = __float2bfloat16(v.w);
            __nv_bfloat16 l0 = __float2bfloat16(v.x - __bfloat162float(h0));
            __nv_bfloat16 l1 = __float2bfloat16(v.y - __bfloat162float(h1));
            __nv_bfloat16 l2 = __float2bfloat16(v.z - __bfloat162float(h2));
            __nv_bfloat16 l3 = __float2bfloat16(v.w - __bfloat162float(h3));
            uint2 hi, lo;
            hi.x = (uint32_t)__bfloat16_as_ushort(h0) | ((uint32_t)__bfloat16_as_ushort(h1) << 16);
            hi.y = (uint32_t)__bfloat16_as_ushort(h2) | ((uint32_t)__bfloat16_as_ushort(h3) << 16);
            lo.x = (uint32_t)__bfloat16_as_ushort(l0) | ((uint32_t)__bfloat16_as_ushort(l1) << 16);
            lo.y = (uint32_t)__bfloat16_as_ushort(l2) | ((uint32_t)__bfloat16_as_ushort(l3) << 16);
            *(uint2*)(sb + OFF_BH + e * AST + j * 8) = hi;
            *(uint2*)(sb + OFF_BL + e * AST + j * 8) = lo;
        }
        __syncthreads();

        #pragma unroll
        for (int kss = 0; kss < 4; kss++) {
            const uint32_t kb = kss * 32;
            uint32_t ah[2][4], al[2][4], bh[2][4], bl[2][4];
            ldsm4(ah[0], aHi + kb);
            ldsm4(ah[1], aHi + 16 * AST + kb);
            ldsm4(al[0], aLo + kb);
            ldsm4(al[1], aLo + 16 * AST + kb);
            ldsm4(bh[0], bHi + kb);
            ldsm4(bh[1], bHi + 16 * AST + kb);
            ldsm4(bl[0], bLo + kb);
            ldsm4(bl[1], bLo + 16 * AST + kb);
            MMA_TERM(ah, bh);
            MMA_TERM(ah, bl);
            MMA_TERM(al, bh);
        }
        __syncthreads();
    }

    // epilogue: fp32 partials to g_psif[ks][row][g*64+col]
    float* dst = g_psif + (size_t)ks * (NI * 4096);
    const int gID = lane >> 2;
    const int tig = lane & 3;
    #pragma unroll
    for (int mt = 0; mt < 2; mt++) {
        #pragma unroll
        for (int nt = 0; nt < 4; nt++) {
            int row = wm * 32 + mt * 16 + gID;
            int col = g * 64 + wn * 32 + nt * 8 + tig * 2;
            if (row < NI)
                *(float2*)&dst[row * 4096 + col] =
                    make_float2(acc[mt][nt][0], acc[mt][nt][1]);
            if (row + 8 < NI)
                *(float2*)&dst[(row + 8) * 4096 + col] =
                    make_float2(acc[mt][nt][2], acc[mt][nt][3]);
        }
    }
}

// ---------------------------------------------------------------------------
// Pack kernel: g_psi = packsplit( SCALE * sum_ks g_psif[ks] )
// ---------------------------------------------------------------------------
__global__ __launch_bounds__(256) void pack_kernel() {
    const int idx = blockIdx.x * 256 + threadIdx.x;   // [0, 121*4096)
    const int N = NI * 4096;
    float v = g_psif[idx] + g_psif[idx + N] + g_psif[idx + 2 * N] + g_psif[idx + 3 * N];
    g_psi[idx] = packsplit(v * PSI_SCALE);
}

// ---------------------------------------------------------------------------
// Conv: 3-term bf16 split GEMM, D = Ah*Bh + Ah*Bl + Al*Bh.
// Tile (l, mtile, u), u fastest. M=128 (b,m), N=64 (g), K=64 (e).
// ---------------------------------------------------------------------------
__global__ __launch_bounds__(256, 3) void conv_kernel(float* __restrict__ out) {
    extern __shared__ __align__(16) char sb[];

    const int tid  = threadIdx.x;
    const int wid  = tid >> 5;
    const int lane = tid & 31;
    const int bid  = blockIdx.x;

    int l = 0;
    #pragma unroll
    for (int t = 1; t <= LMAX; t++)
        if (bid >= c_blk_start[t]) l = t;
    const int d     = 2 * l + 1;
    const int l2    = l * l;
    const int rel   = bid - c_blk_start[l];
    const int mtile = rel / d;
    const int u     = rel - mtile * d;
    const int r0    = mtile * 128;

    {
        const uint4* asrc = (const uint4*)(g_xt + l2 * 32768 + r0 * 64);
        #pragma unroll
        for (int it = 0; it < 8; it++) {
            int idx = it * 256 + tid;
            int r = idx >> 4, j = idx & 15;
            uint4 v = asrc[idx];
            uint2 hi, lo;
            hi.x = __byte_perm(v.x, v.y, 0x5410);
            hi.y = __byte_perm(v.z, v.w, 0x5410);
            lo.x = __byte_perm(v.x, v.y, 0x7632);
            lo.y = __byte_perm(v.z, v.w, 0x7632);
            *(uint2*)(sb + r * AST + j * 8)          = hi;
            *(uint2*)(sb + OFF_AL + r * AST + j * 8) = lo;
        }
        const uint4* bsrc = (const uint4*)(g_psi + (l2 + u) * 4096);
        #pragma unroll
        for (int it = 0; it < 4; it++) {
            int idx = it * 256 + tid;
            int n = idx >> 4, j = idx & 15;
            uint4 v = bsrc[idx];
            uint2 hi, lo;
            hi.x = __byte_perm(v.x, v.y, 0x5410);
            hi.y = __byte_perm(v.z, v.w, 0x5410);
            lo.x = __byte_perm(v.x, v.y, 0x7632);
            lo.y = __byte_perm(v.z, v.w, 0x7632);
            *(uint2*)(sb + OFF_BH + n * AST + j * 8) = hi;
            *(uint2*)(sb + OFF_BL + n * AST + j * 8) = lo;
        }
    }
    __syncthreads();

    const int wm = wid & 3;
    const int wn = wid >> 2;
    const uint32_t rowA = (wm * 32 + (lane & 15)) * AST + (lane >> 4) * 16;
    const uint32_t rowB = (wn * 32 + (lane & 15)) * AST + (lane >> 4) * 16;
    const uint32_t aHi = su32(sb) + rowA;
    const uint32_t aLo = su32(sb) + OFF_AL + rowA;
    const uint32_t bHi = su32(sb) + OFF_BH + rowB;
    const uint32_t bLo = su32(sb) + OFF_BL + rowB;

    float acc[2][4][4];
    #pragma unroll
    for (int mt = 0; mt < 2; mt++)
        #pragma unroll
        for (int nt = 0; nt < 4; nt++)
            #pragma unroll
            for (int q = 0; q < 4; q++) acc[mt][nt][q] = 0.f;

    #pragma unroll
    for (int ks = 0; ks < 4; ks++) {
        const uint32_t kb = ks * 32;
        uint32_t ah[2][4], al[2][4], bh[2][4], bl[2][4];
        ldsm4(ah[0], aHi + kb);
        ldsm4(ah[1], aHi + 16 * AST + kb);
        ldsm4(al[0], aLo + kb);
        ldsm4(al[1], aLo + 16 * AST + kb);
        ldsm4(bh[0], bHi + kb);
        ldsm4(bh[1], bHi + 16 * AST + kb);
        ldsm4(bl[0], bLo + kb);
        ldsm4(bl[1], bLo + 16 * AST + kb);
        MMA_TERM(ah, bh);
        MMA_TERM(ah, bl);
        MMA_TERM(al, bh);
    }

    // epilogue: stage fp32 tile in smem, stride 65
    __syncthreads();
    float* sC = (float*)sb;
    const int gID = lane >> 2;
    const int tig = lane & 3;
    #pragma unroll
    for (int mt = 0; mt < 2; mt++) {
        #pragma unroll
        for (int nt = 0; nt < 4; nt++) {
            int row = wm * 32 + mt * 16 + gID;
            int col = wn * 32 + nt * 8 + tig * 2;
            sC[row * 65 + col]           = acc[mt][nt][0];
            sC[row * 65 + col + 1]       = acc[mt][nt][1];
            sC[(row + 8) * 65 + col]     = acc[mt][nt][2];
            sC[(row + 8) * 65 + col + 1] = acc[mt][nt][3];
        }
    }
    __syncthreads();

    const int offl = c_off[l];
    #pragma unroll
    for (int it = 0; it < 32; it++) {
        int linear = it * 256 + tid;
        int g = linear >> 7;
        int r = linear & 127;
        int R = r0 + r;
        int b = R / d;
        int m = R - b * d;
        out[(size_t)b * (64 * DTOT) + (size_t)g * DTOT + offl + u * d + m]
            = sC[r * 65 + g];
    }
}

// ---------------------------------------------------------------------------
extern "C" void kernel_launch(void* const* d_in, const int* in_sizes, int n_in,
                              void* d_out, int out_size) {
    const float *x = nullptr, *w = nullptr, *Y = nullptr;
    for (int i = 0; i < n_in; i++) {
        if (in_sizes[i] == 512 * 64 * NI)       x = (const float*)d_in[i];
        else if (in_sizes[i] == 64 * 64 * 512)  w = (const float*)d_in[i];
        else if (in_sizes[i] == 512 * NI)       Y = (const float*)d_in[i];
    }
    float* out = (float*)d_out;

    cudaFuncSetAttribute(fused_pre_kernel, cudaFuncAttributeMaxDynamicSharedMemorySize, DSMEM);
    cudaFuncSetAttribute(conv_kernel,      cudaFuncAttributeMaxDynamicSharedMemorySize, DSMEM);

    fused_pre_kernel<<<768, 256, DSMEM>>>(Y, w, x);
    pack_kernel<<<NI * 4096 / 256, 256>>>();
    conv_kernel<<<7084, 256, DSMEM>>>(out);
}

// round 12
// speedup vs baseline: 1.8950x; 1.0694x over previous
#include <cuda_runtime.h>
#include <cuda_bf16.h>
#include <cuda_fp16.h>
#include <cstdint>

#define LMAX 10
#define NI   121
#define DTOT 1771
#define PSI_SCALE 0.005524271728019903f   // 1/(sqrt(512)*sqrt(64))

// scratch
__device__ __half g_xt[512 * 64 * NI];     // [l-block][(b*d+m)][e]  fp16
__device__ __half g_psi[NI * 4096];        // [i][g*64+e]            fp16
__device__ float  g_psif[8 * NI * 4096];   // k-split partials [ks][i][g*64+e]

__constant__ int c_blk_start[12] = {0,4,40,140,336,660,1144,1820,2720,3876,5320,7084};
__constant__ int c_off[11]       = {0,1,10,35,84,165,286,455,680,969,1330};

// ---------------------------------------------------------------------------
__device__ __forceinline__ uint32_t su32(const void* p) {
    return (uint32_t)__cvta_generic_to_shared(p);
}
__device__ __forceinline__ void ldsm4(uint32_t* r, uint32_t addr) {
    asm volatile("ldmatrix.sync.aligned.m8n8.x4.shared.b16 {%0,%1,%2,%3}, [%4];"
                 : "=r"(r[0]), "=r"(r[1]), "=r"(r[2]), "=r"(r[3]) : "r"(addr));
}
__device__ __forceinline__ void mma_bf16(float* c, const uint32_t* a,
                                         uint32_t b0, uint32_t b1) {
    asm volatile(
        "mma.sync.aligned.m16n8k16.row.col.f32.bf16.bf16.f32 "
        "{%0,%1,%2,%3}, {%4,%5,%6,%7}, {%8,%9}, {%0,%1,%2,%3};"
        : "+f"(c[0]), "+f"(c[1]), "+f"(c[2]), "+f"(c[3])
        : "r"(a[0]), "r"(a[1]), "r"(a[2]), "r"(a[3]), "r"(b0), "r"(b1));
}
__device__ __forceinline__ void mma_f16(float* c, const uint32_t* a,
                                        uint32_t b0, uint32_t b1) {
    asm volatile(
        "mma.sync.aligned.m16n8k16.row.col.f32.f16.f16.f32 "
        "{%0,%1,%2,%3}, {%4,%5,%6,%7}, {%8,%9}, {%0,%1,%2,%3};"
        : "+f"(c[0]), "+f"(c[1]), "+f"(c[2]), "+f"(c[3])
        : "r"(a[0]), "r"(a[1]), "r"(a[2]), "r"(a[3]), "r"(b0), "r"(b1));
}

// shared tile geometry (row = 64 vals * 2B = 128B data, padded to 144B)
#define AST      144
#define OFF_AL   18432     // psi kernel: 128*144
#define OFF_BH   36864
#define OFF_BL   46080
#define DSMEM_PRE 55296

#define OFF_B    18432     // conv kernel: B tile after 128-row A tile
#define DSMEM_CONV 33280   // epilogue fp32 tile 128*65*4 dominates

#define MMA_TERM(A, B)                                                   \
    do {                                                                 \
        _Pragma("unroll")                                                \
        for (int mt = 0; mt < 2; mt++) {                                 \
            _Pragma("unroll")                                            \
            for (int h = 0; h < 2; h++) {                                \
                mma_bf16(acc[mt][2 * h + 0], A[mt], B[h][0], B[h][2]);   \
                mma_bf16(acc[mt][2 * h + 1], A[mt], B[h][1], B[h][3]);   \
            }                                                            \
        }                                                                \
    } while (0)

// ---------------------------------------------------------------------------
// Fused pre-kernel: blocks [0,512) = psi k-split (ks = bid>>6, g = bid&63,
// K=64 chunk each, 3-term bf16 split); blocks [512,1024) = x transpose.
// ---------------------------------------------------------------------------
__global__ __launch_bounds__(256) void fused_pre_kernel(const float* __restrict__ Y,
                                                        const float* __restrict__ W,
                                                        const float* __restrict__ x) {
    extern __shared__ __align__(16) char sb[];
    const int tid = threadIdx.x;

    if (blockIdx.x >= 512) {
        // ---------------- transpose role ----------------
        float* s = (float*)sb;
        const int b = blockIdx.x - 512;
        const float* xb = x + b * (64 * NI);
        for (int k = tid; k < 64 * NI; k += 256) s[k] = xb[k];
        __syncthreads();
        for (int k = tid; k < 64 * NI; k += 256) {
            int i = k >> 6, e = k & 63;
            float v = s[e * NI + i];
            int l = (int)sqrtf((float)i + 0.5f);
            int d = 2 * l + 1, m = i - l * l;
            g_xt[32768 * l * l + (b * d + m) * 64 + e] = __float2half_rn(v);
        }
        return;
    }

    // ---------------- psi partial role ----------------
    const int wid  = tid >> 5;
    const int lane = tid & 31;
    const int g    = blockIdx.x & 63;
    const int ks   = blockIdx.x >> 6;
    const int kk   = ks * 64;

    const int wm = wid & 3;
    const int wn = wid >> 2;
    const uint32_t rowA = (wm * 32 + (lane & 15)) * AST + (lane >> 4) * 16;
    const uint32_t rowB = (wn * 32 + (lane & 15)) * AST + (lane >> 4) * 16;
    const uint32_t aHi = su32(sb) + rowA;
    const uint32_t aLo = su32(sb) + OFF_AL + rowA;
    const uint32_t bHi = su32(sb) + OFF_BH + rowB;
    const uint32_t bLo = su32(sb) + OFF_BL + rowB;

    float acc[2][4][4];
    #pragma unroll
    for (int mt = 0; mt < 2; mt++)
        #pragma unroll
        for (int nt = 0; nt < 4; nt++)
            #pragma unroll
            for (int q = 0; q < 4; q++) acc[mt][nt][q] = 0.f;

    // A tile: [i][k] from Y[(kk+k)*121 + i], bf16 hi/lo
    #pragma unroll
    for (int it = 0; it < 16; it++) {
        int idx = it * 256 + tid;
        int kp = idx >> 7;
        int i  = idx & 127;
        float v0 = 0.f, v1 = 0.f;
        if (i < NI) {
            v0 = Y[(kk + 2 * kp) * NI + i];
            v1 = Y[(kk + 2 * kp + 1) * NI + i];
        }
        __nv_bfloat16 h0 = __float2bfloat16(v0);
        __nv_bfloat16 h1 = __float2bfloat16(v1);
        __nv_bfloat16 l0 = __float2bfloat16(v0 - __bfloat162float(h0));
        __nv_bfloat16 l1 = __float2bfloat16(v1 - __bfloat162float(h1));
        *(uint32_t*)(sb + i * AST + kp * 4) =
            (uint32_t)__bfloat16_as_ushort(h0) | ((uint32_t)__bfloat16_as_ushort(h1) << 16);
        *(uint32_t*)(sb + OFF_AL + i * AST + kp * 4) =
            (uint32_t)__bfloat16_as_ushort(l0) | ((uint32_t)__bfloat16_as_ushort(l1) << 16);
    }
    // B tile: [e][k] from W[(e*64+g)*512 + kk + k]
    #pragma unroll
    for (int it = 0; it < 4; it++) {
        int idx = it * 256 + tid;
        int e = idx >> 4, j = idx & 15;
        float4 v = *(const float4*)&W[(size_t)(e * 64 + g) * 512 + kk + j * 4];
        __nv_bfloat16 h0 = __float2bfloat16(v.x), h1 = __float2bfloat16(v.y);
        __nv_bfloat16 h2 = __float2bfloat16(v.z), h3 = __float2bfloat16(v.w);
        __nv_bfloat16 l0 = __float2bfloat16(v.x - __bfloat162float(h0));
        __nv_bfloat16 l1 = __float2bfloat16(v.y - __bfloat162float(h1));
        __nv_bfloat16 l2 = __float2bfloat16(v.z - __bfloat162float(h2));
        __nv_bfloat16 l3 = __float2bfloat16(v.w - __bfloat162float(h3));
        uint2 hi, lo;
        hi.x = (uint32_t)__bfloat16_as_ushort(h0) | ((uint32_t)__bfloat16_as_ushort(h1) << 16);
        hi.y = (uint32_t)__bfloat16_as_ushort(h2) | ((uint32_t)__bfloat16_as_ushort(h3) << 16);
        lo.x = (uint32_t)__bfloat16_as_ushort(l0) | ((uint32_t)__bfloat16_as_ushort(l1) << 16);
        lo.y = (uint32_t)__bfloat16_as_ushort(l2) | ((uint32_t)__bfloat16_as_ushort(l3) << 16);
        *(uint2*)(sb + OFF_BH + e * AST + j * 8) = hi;
        *(uint2*)(sb + OFF_BL + e * AST + j * 8) = lo;
    }
    __syncthreads();

    #pragma unroll
    for (int kss = 0; kss < 4; kss++) {
        const uint32_t kb = kss * 32;
        uint32_t ah[2][4], al[2][4], bh[2][4], bl[2][4];
        ldsm4(ah[0], aHi + kb);
        ldsm4(ah[1], aHi + 16 * AST + kb);
        ldsm4(al[0], aLo + kb);
        ldsm4(al[1], aLo + 16 * AST + kb);
        ldsm4(bh[0], bHi + kb);
        ldsm4(bh[1], bHi + 16 * AST + kb);
        ldsm4(bl[0], bLo + kb);
        ldsm4(bl[1], bLo + 16 * AST + kb);
        MMA_TERM(ah, bh);
        MMA_TERM(ah, bl);
        MMA_TERM(al, bh);
    }

    // epilogue: fp32 partials
    float* dst = g_psif + (size_t)ks * (NI * 4096);
    const int gID = lane >> 2;
    const int tig = lane & 3;
    #pragma unroll
    for (int mt = 0; mt < 2; mt++) {
        #pragma unroll
        for (int nt = 0; nt < 4; nt++) {
            int row = wm * 32 + mt * 16 + gID;
            int col = g * 64 + wn * 32 + nt * 8 + tig * 2;
            if (row < NI)
                *(float2*)&dst[row * 4096 + col] =
                    make_float2(acc[mt][nt][0], acc[mt][nt][1]);
            if (row + 8 < NI)
                *(float2*)&dst[(row + 8) * 4096 + col] =
                    make_float2(acc[mt][nt][2], acc[mt][nt][3]);
        }
    }
}

// ---------------------------------------------------------------------------
// Pack: g_psi = fp16( SCALE * sum_{ks<8} g_psif[ks] )
// ---------------------------------------------------------------------------
__global__ __launch_bounds__(256) void pack_kernel() {
    const int idx = blockIdx.x * 256 + threadIdx.x;
    const int N = NI * 4096;
    float v = 0.f;
    #pragma unroll
    for (int ks = 0; ks < 8; ks++) v += g_psif[idx + ks * N];
    g_psi[idx] = __float2half_rn(v * PSI_SCALE);
}

// ---------------------------------------------------------------------------
// Conv: single-pass fp16 GEMM. Tile (l, mtile, u), u fastest.
// M=128 rows of (b,m), N=64 (g), K=64 (e). 8 warps, warp tile 32x32.
// ---------------------------------------------------------------------------
__global__ __launch_bounds__(256, 4) void conv_kernel(float* __restrict__ out) {
    extern __shared__ __align__(16) char sb[];

    const int tid  = threadIdx.x;
    const int wid  = tid >> 5;
    const int lane = tid & 31;
    const int bid  = blockIdx.x;

    int l = 0;
    #pragma unroll
    for (int t = 1; t <= LMAX; t++)
        if (bid >= c_blk_start[t]) l = t;
    const int d     = 2 * l + 1;
    const int l2    = l * l;
    const int rel   = bid - c_blk_start[l];
    const int mtile = rel / d;
    const int u     = rel - mtile * d;
    const int r0    = mtile * 128;

    // ---- load A (16 KB fp16) and B (8 KB fp16) into padded smem rows
    {
        const uint4* asrc = (const uint4*)(g_xt + (size_t)l2 * 32768 + (size_t)r0 * 64);
        #pragma unroll
        for (int it = 0; it < 4; it++) {
            int idx = it * 256 + tid;          // 1024 chunks: row = idx>>3, j = idx&7
            int r = idx >> 3, j = idx & 7;
            *(uint4*)(sb + r * AST + j * 16) = asrc[idx];
        }
        const uint4* bsrc = (const uint4*)(g_psi + (size_t)(l2 + u) * 4096);
        #pragma unroll
        for (int it = 0; it < 2; it++) {
            int idx = it * 256 + tid;          // 512 chunks
            int n = idx >> 3, j = idx & 7;
            *(uint4*)(sb + OFF_B + n * AST + j * 16) = bsrc[idx];
        }
    }
    __syncthreads();

    const int wm = wid & 3;
    const int wn = wid >> 2;
    const uint32_t aBase = su32(sb) + (wm * 32 + (lane & 15)) * AST + (lane >> 4) * 16;
    const uint32_t bBase = su32(sb) + OFF_B + (wn * 32 + (lane & 15)) * AST + (lane >> 4) * 16;

    float acc[2][4][4];
    #pragma unroll
    for (int mt = 0; mt < 2; mt++)
        #pragma unroll
        for (int nt = 0; nt < 4; nt++)
            #pragma unroll
            for (int q = 0; q < 4; q++) acc[mt][nt][q] = 0.f;

    #pragma unroll
    for (int ks = 0; ks < 4; ks++) {
        const uint32_t kb = ks * 32;
        uint32_t a[2][4], b[2][4];
        ldsm4(a[0], aBase + kb);
        ldsm4(a[1], aBase + 16 * AST + kb);
        ldsm4(b[0], bBase + kb);
        ldsm4(b[1], bBase + 16 * AST + kb);
        #pragma unroll
        for (int mt = 0; mt < 2; mt++) {
            #pragma unroll
            for (int h = 0; h < 2; h++) {
                mma_f16(acc[mt][2 * h + 0], a[mt], b[h][0], b[h][2]);
                mma_f16(acc[mt][2 * h + 1], a[mt], b[h][1], b[h][3]);
            }
        }
    }

    // ---- epilogue: stage fp32 tile in smem, stride 65
    __syncthreads();
    float* sC = (float*)sb;
    const int gID = lane >> 2;
    const int tig = lane & 3;
    #pragma unroll
    for (int mt = 0; mt < 2; mt++) {
        #pragma unroll
        for (int nt = 0; nt < 4; nt++) {
            int row = wm * 32 + mt * 16 + gID;
            int col = wn * 32 + nt * 8 + tig * 2;
            sC[row * 65 + col]           = acc[mt][nt][0];
            sC[row * 65 + col + 1]       = acc[mt][nt][1];
            sC[(row + 8) * 65 + col]     = acc[mt][nt][2];
            sC[(row + 8) * 65 + col + 1] = acc[mt][nt][3];
        }
    }
    __syncthreads();

    const int offl = c_off[l];
    #pragma unroll
    for (int it = 0; it < 32; it++) {
        int linear = it * 256 + tid;
        int g = linear >> 7;
        int r = linear & 127;
        int R = r0 + r;
        int b = R / d;
        int m = R - b * d;
        out[(size_t)b * (64 * DTOT) + (size_t)g * DTOT + offl + u * d + m]
            = sC[r * 65 + g];
    }
}

// ---------------------------------------------------------------------------
extern "C" void kernel_launch(void* const* d_in, const int* in_sizes, int n_in,
                              void* d_out, int out_size) {
    const float *x = nullptr, *w = nullptr, *Y = nullptr;
    for (int i = 0; i < n_in; i++) {
        if (in_sizes[i] == 512 * 64 * NI)       x = (const float*)d_in[i];
        else if (in_sizes[i] == 64 * 64 * 512)  w = (const float*)d_in[i];
        else if (in_sizes[i] == 512 * NI)       Y = (const float*)d_in[i];
    }
    float* out = (float*)d_out;

    cudaFuncSetAttribute(fused_pre_kernel, cudaFuncAttributeMaxDynamicSharedMemorySize, DSMEM_PRE);
    cudaFuncSetAttribute(conv_kernel,      cudaFuncAttributeMaxDynamicSharedMemorySize, DSMEM_CONV);

    fused_pre_kernel<<<1024, 256, DSMEM_PRE>>>(Y, w, x);
    pack_kernel<<<NI * 4096 / 256, 256>>>();
    conv_kernel<<<7084, 256, DSMEM_CONV>>>(out);
}